// round 6
// baseline (speedup 1.0000x reference)
#include <cuda_runtime.h>
#include <cuda_bf16.h>

// GHMC loss, fully fused single kernel, warp-parallel finalize.
// loss = (1/n_nonempty) * sum_b ( bce_sum[b] / count[b] )
// per element: z = sigmoid(x); g = |z - t|; b = min((int)(g*10), 9);
//              bce = softplus(z) - t*z   (softplus via degree-5 poly on [0,1])
//
// Determinism: per-block partials reduced in fixed order, combined via integer
// (fixed-point 2^-18) u64 atomics (order-independent). Last block (ticket)
// finalizes with one warp in parallel, then resets all globals for replays.

#define BINS 10
#define THREADS 256
#define BLOCKS_PER_SM 6
#define GRID (148 * BLOCKS_PER_SM)   // 888
#define FIX_SCALE 262144.0f          // 2^18
#define PACK_BIAS 33554432.0f        // 2^25
#define PACK_SHIFT 25                // bits [0,25): bce fix; [25,32): count
#define PACK_MASK  ((1u << PACK_SHIFT) - 1u)

__device__ unsigned long long g_bin_sum[BINS];   // fixed-point 2^-18
__device__ unsigned long long g_bin_cnt[BINS];
__device__ unsigned int       g_ticket;

__global__ __launch_bounds__(THREADS, BLOCKS_PER_SM)
void ghmc_fused_kernel(const float4* __restrict__ pred4,
                       const int4*   __restrict__ tgt4,
                       int nvec,
                       const float*  __restrict__ pred,
                       const int*    __restrict__ tgt,
                       int ntotal,
                       float* __restrict__ out)
{
    // One u32 per (bin, thread): packed {count:7, bce_fix:25}. Layout
    // [bin][tid] -> bank = tid%32: conflict-free RMW, no atomics in hot loop.
    __shared__ unsigned int s_pack[BINS * THREADS];

    const int tid = threadIdx.x;
#pragma unroll
    for (int b = 0; b < BINS; ++b)
        s_pack[b * THREADS + tid] = 0u;
    __syncthreads();

    const int stride = GRID * THREADS;

    // softplus(z), z in [0,1]: Taylor about 0.5, max abs err ~4e-6.
    auto process = [&](float x, int t) {
        float tf = (float)t;                        // t in {0,1}
        float u  = __expf(-x);
        float z  = __fdividef(1.0f, 1.0f + u);      // sigmoid(x)
        float g  = fabsf(z - tf);
        int   b  = (int)(g * 10.0f);
        b = b > (BINS - 1) ? (BINS - 1) : b;
        float c  = z - 0.5f;
        float sp = 0.00087297f;
        sp = fmaf(sp, c, -0.00401487f);
        sp = fmaf(sp, c, -0.00959280f);
        sp = fmaf(sp, c,  0.11750186f);
        sp = fmaf(sp, c,  0.62245933f);
        sp = fmaf(sp, c,  0.97407699f);             // softplus(z)
        float bce = fmaf(-tf, z, sp);               // softplus(z) - t*z >= 0
        // pack: count-increment folded into the FMA bias (2^25); low-field
        // rounding error < 4 ulp, never carries into the count bits.
        unsigned int add = __float2uint_rn(fmaf(bce, FIX_SCALE, PACK_BIAS));
        s_pack[b * THREADS + tid] += add;           // single smem RMW
    };

    // Main loop: x4 unrolled, all 8 16B streaming loads issued back-to-back
    // (MLP_p1 = 8) before any compute touches them.
    int i = blockIdx.x * THREADS + tid;
    for (; i + 3 * stride < nvec; i += 4 * stride) {
        float4 p0 = __ldcs(&pred4[i]);
        float4 p1 = __ldcs(&pred4[i + stride]);
        float4 p2 = __ldcs(&pred4[i + 2 * stride]);
        float4 p3 = __ldcs(&pred4[i + 3 * stride]);
        int4   t0 = __ldcs(&tgt4[i]);
        int4   t1 = __ldcs(&tgt4[i + stride]);
        int4   t2 = __ldcs(&tgt4[i + 2 * stride]);
        int4   t3 = __ldcs(&tgt4[i + 3 * stride]);
        process(p0.x, t0.x); process(p0.y, t0.y);
        process(p0.z, t0.z); process(p0.w, t0.w);
        process(p1.x, t1.x); process(p1.y, t1.y);
        process(p1.z, t1.z); process(p1.w, t1.w);
        process(p2.x, t2.x); process(p2.y, t2.y);
        process(p2.z, t2.z); process(p2.w, t2.w);
        process(p3.x, t3.x); process(p3.y, t3.y);
        process(p3.z, t3.z); process(p3.w, t3.w);
    }
    for (; i < nvec; i += stride) {
        float4 p = __ldcs(&pred4[i]);
        int4   t = __ldcs(&tgt4[i]);
        process(p.x, t.x); process(p.y, t.y);
        process(p.z, t.z); process(p.w, t.w);
    }
    if (blockIdx.x == 0) {                          // scalar tail
        for (int k = nvec * 4 + tid; k < ntotal; k += THREADS)
            process(pred[k], tgt[k]);
    }

    __syncthreads();

    // Block reduction: warp w handles bins w, w+8 (fixed order), then one
    // u64 integer atomic per bin -> order-independent global result.
    const int wid  = tid >> 5;
    const int lane = tid & 31;
    for (int b = wid; b < BINS; b += 8) {
        unsigned long long s = 0ull;
        unsigned int       c = 0u;
#pragma unroll
        for (int k = lane; k < THREADS; k += 32) {
            unsigned int v = s_pack[b * THREADS + k];
            s += (unsigned long long)(v & PACK_MASK);
            c += (v >> PACK_SHIFT);
        }
#pragma unroll
        for (int off = 16; off; off >>= 1) {
            s += __shfl_down_sync(0xffffffffu, s, off);
            c += __shfl_down_sync(0xffffffffu, c, off);
        }
        if (lane == 0) {
            atomicAdd(&g_bin_sum[b], s);
            atomicAdd(&g_bin_cnt[b], (unsigned long long)c);
        }
    }

    // Order this block's bin atomics before its ticket increment.
    __threadfence();
    __syncthreads();

    if (wid == 0) {
        unsigned int ticket = 0u;
        if (lane == 0) ticket = atomicAdd(&g_ticket, 1u);
        ticket = __shfl_sync(0xffffffffu, ticket, 0);
        if (ticket == GRID - 1) {
            // Warp-parallel finalize: lane b owns bin b.
            double ratio = 0.0;
            int    ne    = 0;
            if (lane < BINS) {
                unsigned long long c = *(volatile unsigned long long*)&g_bin_cnt[lane];
                unsigned long long s = *(volatile unsigned long long*)&g_bin_sum[lane];
                if (c > 0ull) {
                    ne    = 1;
                    ratio = (double)s / ((double)FIX_SCALE * (double)c);
                }
            }
#pragma unroll
            for (int off = 16; off; off >>= 1) {
                ratio += __shfl_down_sync(0xffffffffu, ratio, off);
                ne    += __shfl_down_sync(0xffffffffu, ne, off);
            }
            if (lane == 0) {
                if (ne < 1) ne = 1;
                out[0] = (float)(ratio / (double)ne);
            }
            // Reset for next execution (kernel-boundary ordering covers this).
            if (lane < BINS) {
                g_bin_sum[lane] = 0ull;
                g_bin_cnt[lane] = 0ull;
            }
            if (lane == 0) g_ticket = 0u;
        }
    }
}

extern "C" void kernel_launch(void* const* d_in, const int* in_sizes, int n_in,
                              void* d_out, int out_size)
{
    const float* pred = (const float*)d_in[0];
    const int*   tgt  = (const int*)d_in[1];
    float*       out  = (float*)d_out;
    const int n    = in_sizes[0];
    const int nvec = n >> 2;

    ghmc_fused_kernel<<<GRID, THREADS>>>((const float4*)pred, (const int4*)tgt,
                                         nvec, pred, tgt, n, out);
}

// round 9
// speedup vs baseline: 1.2743x; 1.2743x over previous
#include <cuda_runtime.h>
#include <cuda_bf16.h>

// GHMC loss, fully fused single kernel, warp-parallel finalize.
// loss = (1/n_nonempty) * sum_b ( bce_sum[b] / count[b] )
// per element: z = sigmoid(x) via 0.5*tanh(x/2)+0.5 (1 MUFU);
//              g = |z - t|; b = min((int)(g*10), 9);
//              bce = softplus(z) - t*z   (softplus via degree-5 poly on [0,1])
//
// Determinism: per-block partials reduced in fixed order, combined via integer
// (fixed-point 2^-18) u64 atomics (order-independent). Last block (ticket)
// finalizes with one warp in parallel, then resets all globals for replays.

#define BINS 10
#define THREADS 256
#define GRID 1184                 // 148 SMs * 8 blocks
#define FIX_SCALE 262144.0f       // 2^18
#define PACK_BIAS 33554432.0f     // 2^25
#define PACK_SHIFT 25             // bits [0,25): bce fix; [25,32): count
#define PACK_MASK  ((1u << PACK_SHIFT) - 1u)

__device__ unsigned long long g_bin_sum[BINS];   // fixed-point 2^-18
__device__ unsigned long long g_bin_cnt[BINS];
__device__ unsigned int       g_ticket;

__global__ __launch_bounds__(THREADS, 8)
void ghmc_fused_kernel(const float4* __restrict__ pred4,
                       const int4*   __restrict__ tgt4,
                       int nvec,
                       const float*  __restrict__ pred,
                       const int*    __restrict__ tgt,
                       int ntotal,
                       float* __restrict__ out)
{
    // One u32 per (bin, thread): packed {count:7, bce_fix:25}. Layout
    // [bin][tid] -> bank = tid%32: conflict-free RMW, no atomics in hot loop.
    __shared__ unsigned int s_pack[BINS * THREADS];

    const int tid = threadIdx.x;
#pragma unroll
    for (int b = 0; b < BINS; ++b)
        s_pack[b * THREADS + tid] = 0u;
    __syncthreads();

    const int stride = GRID * THREADS;

    // sigmoid via tanh.approx (single MUFU); softplus(z) on z in [0,1] via
    // degree-5 Taylor about 0.5 (max abs err ~4e-6).
    auto process = [&](float x, int t) {
        float tf = (float)t;                        // t in {0,1}
        float th;
        asm("tanh.approx.f32 %0, %1;" : "=f"(th) : "f"(0.5f * x));
        float z  = fmaf(0.5f, th, 0.5f);            // sigmoid(x)
        float g  = fabsf(z - tf);
        int   b  = (int)(g * 10.0f);
        b = b > (BINS - 1) ? (BINS - 1) : b;
        float c  = z - 0.5f;
        float sp = 0.00087297f;
        sp = fmaf(sp, c, -0.00401487f);
        sp = fmaf(sp, c, -0.00959280f);
        sp = fmaf(sp, c,  0.11750186f);
        sp = fmaf(sp, c,  0.62245933f);
        sp = fmaf(sp, c,  0.97407699f);             // softplus(z)
        float bce = fmaf(-tf, z, sp);               // softplus(z) - t*z >= 0
        // pack: count-increment folded into the FMA bias (2^25); low-field
        // rounding error < 4 ulp, never carries into the count bits.
        unsigned int add = __float2uint_rn(fmaf(bce, FIX_SCALE, PACK_BIAS));
        s_pack[b * THREADS + tid] += add;           // single smem RMW
    };

#pragma unroll 2
    for (int i = blockIdx.x * THREADS + tid; i < nvec; i += stride) {
        float4 p = pred4[i];
        int4   t = tgt4[i];
        process(p.x, t.x);
        process(p.y, t.y);
        process(p.z, t.z);
        process(p.w, t.w);
    }
    if (blockIdx.x == 0) {                          // scalar tail
        for (int k = nvec * 4 + tid; k < ntotal; k += THREADS)
            process(pred[k], tgt[k]);
    }

    __syncthreads();

    // Block reduction: warp w handles bins w, w+8 (fixed order), then one
    // u64 integer atomic per bin -> order-independent global result.
    const int wid  = tid >> 5;
    const int lane = tid & 31;
    for (int b = wid; b < BINS; b += 8) {
        unsigned long long s = 0ull;
        unsigned int       c = 0u;
#pragma unroll
        for (int k = lane; k < THREADS; k += 32) {
            unsigned int v = s_pack[b * THREADS + k];
            s += (unsigned long long)(v & PACK_MASK);
            c += (v >> PACK_SHIFT);
        }
#pragma unroll
        for (int off = 16; off; off >>= 1) {
            s += __shfl_down_sync(0xffffffffu, s, off);
            c += __shfl_down_sync(0xffffffffu, c, off);
        }
        if (lane == 0) {
            atomicAdd(&g_bin_sum[b], s);
            atomicAdd(&g_bin_cnt[b], (unsigned long long)c);
        }
    }

    // Order this block's bin atomics before its ticket increment.
    __threadfence();
    __syncthreads();

    if (wid == 0) {
        unsigned int ticket = 0u;
        if (lane == 0) ticket = atomicAdd(&g_ticket, 1u);
        ticket = __shfl_sync(0xffffffffu, ticket, 0);
        if (ticket == GRID - 1) {
            // Warp-parallel finalize: lane b owns bin b.
            double ratio = 0.0;
            int    ne    = 0;
            if (lane < BINS) {
                unsigned long long c = *(volatile unsigned long long*)&g_bin_cnt[lane];
                unsigned long long s = *(volatile unsigned long long*)&g_bin_sum[lane];
                if (c > 0ull) {
                    ne    = 1;
                    ratio = (double)s / ((double)FIX_SCALE * (double)c);
                }
            }
#pragma unroll
            for (int off = 16; off; off >>= 1) {
                ratio += __shfl_down_sync(0xffffffffu, ratio, off);
                ne    += __shfl_down_sync(0xffffffffu, ne, off);
            }
            if (lane == 0) {
                if (ne < 1) ne = 1;
                out[0] = (float)(ratio / (double)ne);
            }
            // Reset for next execution (kernel-boundary ordering covers this).
            if (lane < BINS) {
                g_bin_sum[lane] = 0ull;
                g_bin_cnt[lane] = 0ull;
            }
            if (lane == 0) g_ticket = 0u;
        }
    }
}

extern "C" void kernel_launch(void* const* d_in, const int* in_sizes, int n_in,
                              void* d_out, int out_size)
{
    const float* pred = (const float*)d_in[0];
    const int*   tgt  = (const int*)d_in[1];
    float*       out  = (float*)d_out;
    const int n    = in_sizes[0];
    const int nvec = n >> 2;

    ghmc_fused_kernel<<<GRID, THREADS>>>((const float4*)pred, (const int4*)tgt,
                                         nvec, pred, tgt, n, out);
}

// round 10
// speedup vs baseline: 1.2808x; 1.0051x over previous
#include <cuda_runtime.h>
#include <cuda_bf16.h>

// GHMC loss, fully fused single kernel.
// cp.async double-buffered staging: gmem -> smem with no destination
// registers, decoupling DRAM request depth from the 32-reg / occ-8 budget.
// loss = (1/n_nonempty) * sum_b ( bce_sum[b] / count[b] )
// per element: z = sigmoid(x) via 0.5*tanh(x/2)+0.5 (1 MUFU);
//              b = min((int)(|z-t|*10), 9); bce = softplus(z) - t*z (poly).
//
// Determinism: fixed-order block reduction -> fixed-point u64 atomics
// (order-independent) -> last-block (ticket) warp-parallel finalize + reset.

#define BINS 10
#define THREADS 256
#define GRID 1184                 // 148 SMs * 8 blocks
#define FIX_SCALE 262144.0f       // 2^18
#define PACK_BIAS 33554432.0f     // 2^25
#define PACK_SHIFT 25             // bits [0,25): bce fix; [25,32): count
#define PACK_MASK  ((1u << PACK_SHIFT) - 1u)

__device__ unsigned long long g_bin_sum[BINS];   // fixed-point 2^-18
__device__ unsigned long long g_bin_cnt[BINS];
__device__ unsigned int       g_ticket;

__device__ __forceinline__ void cpa16(void* dst_smem, const void* src, int pred)
{
    unsigned int d = (unsigned int)__cvta_generic_to_shared(dst_smem);
    asm volatile(
        "{\n\t.reg .pred p;\n\t"
        "setp.ne.s32 p, %2, 0;\n\t"
        "@p cp.async.cg.shared.global [%0], [%1], 16;\n\t}"
        :: "r"(d), "l"(src), "r"(pred) : "memory");
}
#define CP_COMMIT() asm volatile("cp.async.commit_group;" ::: "memory")
#define CP_WAIT1()  asm volatile("cp.async.wait_group 1;" ::: "memory")

__global__ __launch_bounds__(THREADS, 8)
void ghmc_fused_kernel(const float4* __restrict__ pred4,
                       const int4*   __restrict__ tgt4,
                       int nvec,
                       const float*  __restrict__ pred,
                       const int*    __restrict__ tgt,
                       int ntotal,
                       float* __restrict__ out)
{
    // Histogram: one u32 per (bin, thread), packed {count:7, bce_fix:25}.
    // [bin][tid] -> bank = tid%32: conflict-free RMW, no atomics in hot loop.
    __shared__ unsigned int s_pack[BINS * THREADS];
    // Double-buffered stage: 16 B per thread per array per stage.
    __shared__ float4 s_p[2][THREADS];
    __shared__ int4   s_t[2][THREADS];

    const int tid = threadIdx.x;
#pragma unroll
    for (int b = 0; b < BINS; ++b)
        s_pack[b * THREADS + tid] = 0u;
    __syncthreads();

    const int stride = GRID * THREADS;

    auto process = [&](float x, int t) {
        float tf = (float)t;                        // t in {0,1}
        float th;
        asm("tanh.approx.f32 %0, %1;" : "=f"(th) : "f"(0.5f * x));
        float z  = fmaf(0.5f, th, 0.5f);            // sigmoid(x)
        float g  = fabsf(z - tf);
        int   b  = (int)(g * 10.0f);
        b = b > (BINS - 1) ? (BINS - 1) : b;
        float c  = z - 0.5f;
        float sp = 0.00087297f;
        sp = fmaf(sp, c, -0.00401487f);
        sp = fmaf(sp, c, -0.00959280f);
        sp = fmaf(sp, c,  0.11750186f);
        sp = fmaf(sp, c,  0.62245933f);
        sp = fmaf(sp, c,  0.97407699f);             // softplus(z)
        float bce = fmaf(-tf, z, sp);               // softplus(z) - t*z >= 0
        unsigned int add = __float2uint_rn(fmaf(bce, FIX_SCALE, PACK_BIAS));
        s_pack[b * THREADS + tid] += add;           // single smem RMW
    };

    const int i0    = blockIdx.x * THREADS + tid;
    const int avail = nvec - blockIdx.x * THREADS;
    const int niter = avail > 0 ? (avail + stride - 1) / stride : 0;

    // Prologue: stage 0.
    cpa16(&s_p[0][tid], &pred4[i0], i0 < nvec);
    cpa16(&s_t[0][tid], &tgt4[i0],  i0 < nvec);
    CP_COMMIT();

    for (int k = 0; k < niter; ++k) {
        // Issue stage k+1 into the other buffer (predicated).
        if (k + 1 < niter) {
            int inext = i0 + (k + 1) * stride;
            int s     = (k + 1) & 1;
            cpa16(&s_p[s][tid], &pred4[inext], inext < nvec);
            cpa16(&s_t[s][tid], &tgt4[inext],  inext < nvec);
        }
        CP_COMMIT();            // uniform group count even when empty
        CP_WAIT1();             // stage k landed (<=1 group pending)
        __syncthreads();

        int i = i0 + k * stride;
        if (i < nvec) {
            int    s = k & 1;
            float4 p = s_p[s][tid];
            int4   t = s_t[s][tid];
            process(p.x, t.x);
            process(p.y, t.y);
            process(p.z, t.z);
            process(p.w, t.w);
        }
        __syncthreads();        // reads done before buffer is overwritten
    }

    if (blockIdx.x == 0) {                          // scalar gmem tail
        for (int k = nvec * 4 + tid; k < ntotal; k += THREADS)
            process(pred[k], tgt[k]);
    }

    __syncthreads();

    // Block reduction: warp w handles bins w, w+8 (fixed order), then one
    // u64 integer atomic per bin -> order-independent global result.
    const int wid  = tid >> 5;
    const int lane = tid & 31;
    for (int b = wid; b < BINS; b += 8) {
        unsigned long long s = 0ull;
        unsigned int       c = 0u;
#pragma unroll
        for (int k = lane; k < THREADS; k += 32) {
            unsigned int v = s_pack[b * THREADS + k];
            s += (unsigned long long)(v & PACK_MASK);
            c += (v >> PACK_SHIFT);
        }
#pragma unroll
        for (int off = 16; off; off >>= 1) {
            s += __shfl_down_sync(0xffffffffu, s, off);
            c += __shfl_down_sync(0xffffffffu, c, off);
        }
        if (lane == 0) {
            atomicAdd(&g_bin_sum[b], s);
            atomicAdd(&g_bin_cnt[b], (unsigned long long)c);
        }
    }

    // Order this block's bin atomics before its ticket increment.
    __threadfence();
    __syncthreads();

    if (wid == 0) {
        unsigned int ticket = 0u;
        if (lane == 0) ticket = atomicAdd(&g_ticket, 1u);
        ticket = __shfl_sync(0xffffffffu, ticket, 0);
        if (ticket == GRID - 1) {
            // Warp-parallel finalize: lane b owns bin b.
            double ratio = 0.0;
            int    ne    = 0;
            if (lane < BINS) {
                unsigned long long c = *(volatile unsigned long long*)&g_bin_cnt[lane];
                unsigned long long s = *(volatile unsigned long long*)&g_bin_sum[lane];
                if (c > 0ull) {
                    ne    = 1;
                    ratio = (double)s / ((double)FIX_SCALE * (double)c);
                }
            }
#pragma unroll
            for (int off = 16; off; off >>= 1) {
                ratio += __shfl_down_sync(0xffffffffu, ratio, off);
                ne    += __shfl_down_sync(0xffffffffu, ne, off);
            }
            if (lane == 0) {
                if (ne < 1) ne = 1;
                out[0] = (float)(ratio / (double)ne);
            }
            // Reset for next execution (kernel-boundary ordering covers this).
            if (lane < BINS) {
                g_bin_sum[lane] = 0ull;
                g_bin_cnt[lane] = 0ull;
            }
            if (lane == 0) g_ticket = 0u;
        }
    }
}

extern "C" void kernel_launch(void* const* d_in, const int* in_sizes, int n_in,
                              void* d_out, int out_size)
{
    const float* pred = (const float*)d_in[0];
    const int*   tgt  = (const int*)d_in[1];
    float*       out  = (float*)d_out;
    const int n    = in_sizes[0];
    const int nvec = n >> 2;

    ghmc_fused_kernel<<<GRID, THREADS>>>((const float4*)pred, (const int4*)tgt,
                                         nvec, pred, tgt, n, out);
}

// round 11
// speedup vs baseline: 1.3612x; 1.0628x over previous
#include <cuda_runtime.h>
#include <cuda_bf16.h>

// GHMC loss, fully fused single kernel.
// Barrier-free 5-stage cp.async pipeline: each thread stages ITS OWN 16B+16B
// per stage and reads back only its own data, so cp.async per-thread group
// semantics replace __syncthreads entirely. 4 CTAs/SM (smem-capped) with
// 4 stages outstanding -> ~131KB DRAM requests in flight per SM.
//
// per element: z = sigmoid(x) via 0.5*tanh(x/2)+0.5 (1 MUFU);
//              b = min((int)(|z-t|*10), 9); bce = softplus(z) - t*z (poly).
// loss = (1/n_nonempty) * sum_b ( bce_sum[b] / count[b] )
//
// Determinism: fixed-order block reduction -> fixed-point u64 atomics
// (order-independent) -> last-block (ticket) warp-parallel finalize + reset.

#define BINS 10
#define THREADS 256
#define BLOCKS_PER_SM 4
#define GRID (148 * BLOCKS_PER_SM)   // 592
#define STAGES 5
#define FIX_SCALE 262144.0f          // 2^18
#define PACK_BIAS 33554432.0f        // 2^25
#define PACK_SHIFT 25                // bits [0,25): bce fix; [25,32): count
#define PACK_MASK  ((1u << PACK_SHIFT) - 1u)

__device__ unsigned long long g_bin_sum[BINS];   // fixed-point 2^-18
__device__ unsigned long long g_bin_cnt[BINS];
__device__ unsigned int       g_ticket;

__device__ __forceinline__ void cpa16(void* dst_smem, const void* src, int pred)
{
    unsigned int d = (unsigned int)__cvta_generic_to_shared(dst_smem);
    asm volatile(
        "{\n\t.reg .pred p;\n\t"
        "setp.ne.s32 p, %2, 0;\n\t"
        "@p cp.async.cg.shared.global [%0], [%1], 16;\n\t}"
        :: "r"(d), "l"(src), "r"(pred) : "memory");
}
#define CP_COMMIT() asm volatile("cp.async.commit_group;" ::: "memory")
#define CP_WAIT()   asm volatile("cp.async.wait_group %0;" :: "n"(STAGES - 1) : "memory")

__global__ __launch_bounds__(THREADS, BLOCKS_PER_SM)
void ghmc_fused_kernel(const float4* __restrict__ pred4,
                       const int4*   __restrict__ tgt4,
                       int nvec,
                       const float*  __restrict__ pred,
                       const int*    __restrict__ tgt,
                       int ntotal,
                       float* __restrict__ out)
{
    // Histogram: one u32 per (bin, thread), packed {count:7, bce_fix:25}.
    // [bin][tid] -> bank = tid%32: conflict-free RMW, no atomics in hot loop.
    __shared__ unsigned int s_pack[BINS * THREADS];
    // 5-stage staging buffers: 16B per thread per array per stage.
    __shared__ float4 s_p[STAGES][THREADS];
    __shared__ int4   s_t[STAGES][THREADS];

    const int tid = threadIdx.x;
#pragma unroll
    for (int b = 0; b < BINS; ++b)
        s_pack[b * THREADS + tid] = 0u;
    __syncthreads();   // histogram zeroed before any RMW (only barrier needed)

    const int stride = GRID * THREADS;

    auto process = [&](float x, int t) {
        float tf = (float)t;                        // t in {0,1}
        float th;
        asm("tanh.approx.f32 %0, %1;" : "=f"(th) : "f"(0.5f * x));
        float z  = fmaf(0.5f, th, 0.5f);            // sigmoid(x)
        float g  = fabsf(z - tf);
        int   b  = (int)(g * 10.0f);
        b = b > (BINS - 1) ? (BINS - 1) : b;
        float c  = z - 0.5f;
        float sp = 0.00087297f;
        sp = fmaf(sp, c, -0.00401487f);
        sp = fmaf(sp, c, -0.00959280f);
        sp = fmaf(sp, c,  0.11750186f);
        sp = fmaf(sp, c,  0.62245933f);
        sp = fmaf(sp, c,  0.97407699f);             // softplus(z)
        float bce = fmaf(-tf, z, sp);               // softplus(z) - t*z >= 0
        unsigned int add = __float2uint_rn(fmaf(bce, FIX_SCALE, PACK_BIAS));
        s_pack[b * THREADS + tid] += add;           // single smem RMW
    };

    const int i0    = blockIdx.x * THREADS + tid;
    const int avail = nvec - blockIdx.x * THREADS;
    const int niter = avail > 0 ? (avail + stride - 1) / stride : 0;

    // Prologue: issue stages 0..STAGES-2, one commit group each.
#pragma unroll
    for (int j = 0; j < STAGES - 1; ++j) {
        int i = i0 + j * stride;
        cpa16(&s_p[j][tid], &pred4[i], i < nvec);
        cpa16(&s_t[j][tid], &tgt4[i],  i < nvec);
        CP_COMMIT();
    }

    int ws = STAGES - 1;   // write slot
    int rs = 0;            // read slot
    for (int k = 0; k < niter; ++k) {
        // Issue stage k+STAGES-1 (predicated), keep group count uniform.
        int inext = i0 + (k + STAGES - 1) * stride;
        cpa16(&s_p[ws][tid], &pred4[inext], inext < nvec);
        cpa16(&s_t[ws][tid], &tgt4[inext],  inext < nvec);
        CP_COMMIT();
        CP_WAIT();          // stage k landed (per-thread semantics, no barrier)

        int i = i0 + k * stride;
        if (i < nvec) {
            float4 p = s_p[rs][tid];
            int4   t = s_t[rs][tid];
            process(p.x, t.x);
            process(p.y, t.y);
            process(p.z, t.z);
            process(p.w, t.w);
        }
        ws = (ws + 1 == STAGES) ? 0 : ws + 1;
        rs = (rs + 1 == STAGES) ? 0 : rs + 1;
    }

    if (blockIdx.x == 0) {                          // scalar gmem tail
        for (int k = nvec * 4 + tid; k < ntotal; k += THREADS)
            process(pred[k], tgt[k]);
    }

    __syncthreads();

    // Block reduction: warp w handles bins w, w+8 (fixed order), then one
    // u64 integer atomic per bin -> order-independent global result.
    const int wid  = tid >> 5;
    const int lane = tid & 31;
    for (int b = wid; b < BINS; b += 8) {
        unsigned long long s = 0ull;
        unsigned int       c = 0u;
#pragma unroll
        for (int k = lane; k < THREADS; k += 32) {
            unsigned int v = s_pack[b * THREADS + k];
            s += (unsigned long long)(v & PACK_MASK);
            c += (v >> PACK_SHIFT);
        }
#pragma unroll
        for (int off = 16; off; off >>= 1) {
            s += __shfl_down_sync(0xffffffffu, s, off);
            c += __shfl_down_sync(0xffffffffu, c, off);
        }
        if (lane == 0) {
            atomicAdd(&g_bin_sum[b], s);
            atomicAdd(&g_bin_cnt[b], (unsigned long long)c);
        }
    }

    // Order this block's bin atomics before its ticket increment.
    __threadfence();
    __syncthreads();

    if (wid == 0) {
        unsigned int ticket = 0u;
        if (lane == 0) ticket = atomicAdd(&g_ticket, 1u);
        ticket = __shfl_sync(0xffffffffu, ticket, 0);
        if (ticket == GRID - 1) {
            // Warp-parallel finalize: lane b owns bin b.
            double ratio = 0.0;
            int    ne    = 0;
            if (lane < BINS) {
                unsigned long long c = *(volatile unsigned long long*)&g_bin_cnt[lane];
                unsigned long long s = *(volatile unsigned long long*)&g_bin_sum[lane];
                if (c > 0ull) {
                    ne    = 1;
                    ratio = (double)s / ((double)FIX_SCALE * (double)c);
                }
            }
#pragma unroll
            for (int off = 16; off; off >>= 1) {
                ratio += __shfl_down_sync(0xffffffffu, ratio, off);
                ne    += __shfl_down_sync(0xffffffffu, ne, off);
            }
            if (lane == 0) {
                if (ne < 1) ne = 1;
                out[0] = (float)(ratio / (double)ne);
            }
            // Reset for next execution (kernel-boundary ordering covers this).
            if (lane < BINS) {
                g_bin_sum[lane] = 0ull;
                g_bin_cnt[lane] = 0ull;
            }
            if (lane == 0) g_ticket = 0u;
        }
    }
}

extern "C" void kernel_launch(void* const* d_in, const int* in_sizes, int n_in,
                              void* d_out, int out_size)
{
    const float* pred = (const float*)d_in[0];
    const int*   tgt  = (const int*)d_in[1];
    float*       out  = (float*)d_out;
    const int n    = in_sizes[0];
    const int nvec = n >> 2;

    ghmc_fused_kernel<<<GRID, THREADS>>>((const float4*)pred, (const int4*)tgt,
                                         nvec, pred, tgt, n, out);
}